// round 14
// baseline (speedup 1.0000x reference)
#include <cuda_runtime.h>
#include <cstdint>
#include <cstddef>

typedef unsigned long long ull;

// ---------------------------------------------------------------------------
// Packed f32x2 helpers (SASS FFMA2 path — only reachable via explicit PTX)
// ---------------------------------------------------------------------------
__device__ __forceinline__ ull fma2(ull a, ull b, ull c) {
    ull d; asm("fma.rn.f32x2 %0,%1,%2,%3;" : "=l"(d) : "l"(a), "l"(b), "l"(c)); return d;
}
__device__ __forceinline__ ull mul2(ull a, ull b) {
    ull d; asm("mul.rn.f32x2 %0,%1,%2;" : "=l"(d) : "l"(a), "l"(b)); return d;
}
__device__ __forceinline__ ull pack2(float lo, float hi) {
    ull d; asm("mov.b64 %0,{%1,%2};" : "=l"(d) : "f"(lo), "f"(hi)); return d;
}
__device__ __forceinline__ ull dup2(float x) {
    ull d; asm("mov.b64 %0,{%1,%1};" : "=l"(d) : "f"(x)); return d;
}
__device__ __forceinline__ void unpack2(ull a, float& lo, float& hi) {
    asm("mov.b64 {%0,%1},%2;" : "=f"(lo), "=f"(hi) : "l"(a));
}
__device__ __forceinline__ ull neg2(ull a) { return a ^ 0x8000000080000000ULL; }

// ---------------------------------------------------------------------------
// Compile-time PGA(3,0,1) tables. Blade order matches the reference:
// idx : (), e0,e1,e2,e3, e01,e02,e03,e12,e13,e23, e012,e013,e023,e123, e0123
// ---------------------------------------------------------------------------
namespace ga {

__host__ __device__ constexpr unsigned bladeMask(int i) {
    constexpr unsigned m[16] = {0u,1u,2u,4u,8u, 3u,5u,9u,6u,10u,12u, 7u,11u,13u,14u, 15u};
    return m[i];
}
__host__ __device__ constexpr int idxOfMask(unsigned m) {
    constexpr int t[16] = {0,1,2,5,3,6,8,11,4,7,9,12,10,13,14,15};
    return t[m];
}
__host__ __device__ constexpr int invCnt(unsigned a, unsigned b) {
    int s = 0;
    for (int i = 0; i < 4; ++i)
        if ((b >> i) & 1u)
            for (int j = i + 1; j < 4; ++j)
                if ((a >> j) & 1u) ++s;
    return s;
}
__host__ __device__ constexpr float gpSign(int j, int k) {
    unsigned a = bladeMask(j), b = bladeMask(k);
    if (a & b & 1u) return 0.0f;                   // e0*e0 = 0
    return (invCnt(a, b) & 1) ? -1.0f : 1.0f;
}
__host__ __device__ constexpr int gpTgt(int j, int k) {
    return idxOfMask(bladeMask(j) ^ bladeMask(k));
}
__host__ __device__ constexpr float dSign(int t) {
    unsigned m = bladeMask(t);
    return (invCnt(m, 15u ^ m) & 1) ? -1.0f : 1.0f;
}
__host__ __device__ constexpr float jnCoef(int b, int c) {
    unsigned mb = bladeMask(b), mc = bladeMask(c);
    if ((mb | mc) != 15u) return 0.0f;
    unsigned ma = mb & mc;
    int ia = idxOfMask(15u ^ ma);
    unsigned cb = 15u ^ mb, cc = 15u ^ mc;
    float so = (invCnt(cb, cc) & 1) ? -1.0f : 1.0f;
    return dSign(ia) * so * dSign(b) * dSign(c);
}
__host__ __device__ constexpr int jnTgt(int b, int c) {
    return idxOfMask(bladeMask(b) & bladeMask(c));
}

template<int...> struct iseq {};
template<int N, int... S> struct mkseq : mkseq<N-1, N-1, S...> {};
template<int... S> struct mkseq<0, S...> { using type = iseq<S...>; };

// Row-local negation: only neg2(L[J]) for the CURRENT row is live.
template<int J, int K>
__device__ __forceinline__ void gpTerm(ull aj, ull naj, const ull (&R)[16], ull (&h)[16]) {
    constexpr float s = gpSign(J, K);
    if constexpr (s > 0.5f) {
        constexpr int t = gpTgt(J, K);
        h[t] = fma2(aj, R[K], h[t]);
    } else if constexpr (s < -0.5f) {
        constexpr int t = gpTgt(J, K);
        h[t] = fma2(naj, R[K], h[t]);
    }
}
template<int J, int... Ks>
__device__ __forceinline__ void gpRow(const ull (&L)[16], const ull (&R)[16],
                                      ull (&h)[16], iseq<Ks...>) {
    const ull aj  = L[J];
    const ull naj = neg2(aj);
    (gpTerm<J, Ks>(aj, naj, R, h), ...);
}
template<int... Js>
__device__ __forceinline__ void gpAll(const ull (&L)[16], const ull (&R)[16],
                                      ull (&h)[16], iseq<Js...>) {
    (gpRow<Js>(L, R, h, typename mkseq<16>::type{}), ...);
}

template<int J, int K>
__device__ __forceinline__ void jnTerm(ull aj, ull naj, const ull (&R)[16], ull (&h)[16]) {
    constexpr float s = jnCoef(J, K);
    if constexpr (s > 0.5f) {
        constexpr int t = jnTgt(J, K);
        h[t] = fma2(aj, R[K], h[t]);
    } else if constexpr (s < -0.5f) {
        constexpr int t = jnTgt(J, K);
        h[t] = fma2(naj, R[K], h[t]);
    }
}
template<int J, int... Ks>
__device__ __forceinline__ void jnRow(const ull (&L)[16], const ull (&R)[16],
                                      ull (&h)[16], iseq<Ks...>) {
    const ull aj  = L[J];
    const ull naj = neg2(aj);
    (jnTerm<J, Ks>(aj, naj, R, h), ...);
}
template<int... Js>
__device__ __forceinline__ void jnAll(const ull (&L)[16], const ull (&R)[16],
                                      ull (&h)[16], iseq<Js...>) {
    (jnRow<Js>(L, R, h, typename mkseq<16>::type{}), ...);
}

// Equivariant-linear accumulation (packed pair), one input channel.
// grades = [0,1,1,1,1, 2,2,2,2,2,2, 3,3,3,3, 4]
// e0 wedge (+1): 1<-0 (w5); 5,6,7<-2,3,4 (w6); 11,12,13<-8,9,10 (w7); 15<-14 (w8)
__device__ __forceinline__ void linAcc2(ull (&o)[16], const ull (&w)[9], const ull (&x)[16]) {
    o[0]  = fma2(w[0], x[0],  o[0]);
    o[1]  = fma2(w[1], x[1],  o[1]);  o[1]  = fma2(w[5], x[0],  o[1]);
    o[2]  = fma2(w[1], x[2],  o[2]);
    o[3]  = fma2(w[1], x[3],  o[3]);
    o[4]  = fma2(w[1], x[4],  o[4]);
    o[5]  = fma2(w[2], x[5],  o[5]);  o[5]  = fma2(w[6], x[2],  o[5]);
    o[6]  = fma2(w[2], x[6],  o[6]);  o[6]  = fma2(w[6], x[3],  o[6]);
    o[7]  = fma2(w[2], x[7],  o[7]);  o[7]  = fma2(w[6], x[4],  o[7]);
    o[8]  = fma2(w[2], x[8],  o[8]);
    o[9]  = fma2(w[2], x[9],  o[9]);
    o[10] = fma2(w[2], x[10], o[10]);
    o[11] = fma2(w[3], x[11], o[11]); o[11] = fma2(w[7], x[8],  o[11]);
    o[12] = fma2(w[3], x[12], o[12]); o[12] = fma2(w[7], x[9],  o[12]);
    o[13] = fma2(w[3], x[13], o[13]); o[13] = fma2(w[7], x[10], o[13]);
    o[14] = fma2(w[3], x[14], o[14]);
    o[15] = fma2(w[4], x[15], o[15]); o[15] = fma2(w[8], x[14], o[15]);
}

} // namespace ga

// ---------------------------------------------------------------------------
// g_P[tok][160]: per-token scalar-head results
//   [0:32)=A0, [32:64)=B0, [64:96)=O0, [96:128)=s1, [128:160)=s2
// ---------------------------------------------------------------------------
#define MAX_TOK 32768
__device__ float g_P[MAX_TOK * 160];

// Scalar-head matmul [ntok,64] @ [64,160] -> g_P.
// Per-block fused transpose into smem with TROW=165 (165 mod 32 = 5,
// gcd(5,32)=1): consecutive-s writes AND lane-indexed reads are both
// conflict-free. 8 tokens (4 packed pairs) per warp; NO min-blocks cap
// (R12's __launch_bounds__(256,1) was the occupancy bug; R13's (256,3)
// was the spill bug).
#define TROW 165
__global__ void __launch_bounds__(256)
scalar_head_kernel(const float* __restrict__ scal,
                   const float* __restrict__ wLs, const float* __restrict__ wRs,
                   const float* __restrict__ wJLs, const float* __restrict__ wJRs,
                   const float* __restrict__ wS2mv, const float* __restrict__ wS2s,
                   int ntok)
{
    __shared__ float T[64 * TROW];         // ~42.2 KB -> 2 blocks/SM (regs)
    const int tid = threadIdx.x;

    // Coalesced global reads, conflict-free transposed smem writes.
    // c layout per s-row: [0:16)=wLs, [16:32)=wJLs, [32:48)=wRs, [48:64)=wJRs,
    //                     [64:96)=wS2mv, [96:160)=wS2s rows 0..63
    for (int i = tid; i < 1024; i += 256) {
        const int k = i >> 6, s = i & 63;
        T[s * TROW +      k] = wLs[i];
        T[s * TROW + 16 + k] = wJLs[i];
        T[s * TROW + 32 + k] = wRs[i];
        T[s * TROW + 48 + k] = wJRs[i];
    }
    for (int i = tid; i < 2048; i += 256) {
        const int k = i >> 6, s = i & 63;
        T[s * TROW + 64 + k] = wS2mv[i];
    }
    for (int i = tid; i < 4096; i += 256) {
        const int k = i >> 6, s = i & 63;
        T[s * TROW + 96 + k] = wS2s[i];
    }
    __syncthreads();

    const int lane = tid & 31;
    const int wid  = tid >> 5;
    const int gw   = blockIdx.x * 8 + wid;
    const int nw   = gridDim.x * 8;
    const int noct = ntok >> 3;            // 8 tokens per unit

    for (int o = gw; o < noct; o += nw) {
        const int t0 = o * 8;
        ull acc[5][4];
        #pragma unroll
        for (int g = 0; g < 5; ++g)
            #pragma unroll
            for (int u = 0; u < 4; ++u) acc[g][u] = 0ULL;

        for (int s4 = 0; s4 < 16; ++s4) {
            float4 sv[8];
            #pragma unroll
            for (int t = 0; t < 8; ++t)
                sv[t] = __ldg(reinterpret_cast<const float4*>(scal + (size_t)(t0 + t) * 64) + s4);
            #pragma unroll
            for (int k = 0; k < 4; ++k) {
                const int s = s4 * 4 + k;
                const float* ts = T + s * TROW + lane;
                const ull w0 = dup2(ts[0]);
                const ull w1 = dup2(ts[32]);
                const ull w2 = dup2(ts[64]);
                const ull w3 = dup2(ts[96]);
                const ull w4 = dup2(ts[128]);
                #pragma unroll
                for (int u = 0; u < 4; ++u) {
                    const float xa = (k == 0) ? sv[2*u].x : (k == 1) ? sv[2*u].y
                                   : (k == 2) ? sv[2*u].z : sv[2*u].w;
                    const float xb = (k == 0) ? sv[2*u+1].x : (k == 1) ? sv[2*u+1].y
                                   : (k == 2) ? sv[2*u+1].z : sv[2*u+1].w;
                    const ull x = pack2(xa, xb);
                    acc[0][u] = fma2(w0, x, acc[0][u]);
                    acc[1][u] = fma2(w1, x, acc[1][u]);
                    acc[2][u] = fma2(w2, x, acc[2][u]);
                    acc[3][u] = fma2(w3, x, acc[3][u]);
                    acc[4][u] = fma2(w4, x, acc[4][u]);
                }
            }
        }
        #pragma unroll
        for (int u = 0; u < 4; ++u) {
            float* pa = g_P + (size_t)(t0 + 2*u)     * 160 + lane;
            float* pb = g_P + (size_t)(t0 + 2*u + 1) * 160 + lane;
            #pragma unroll
            for (int g = 0; g < 5; ++g) {
                float a, b;
                unpack2(acc[g][u], a, b);
                pa[g * 32] = a;
                pb[g * 32] = b;
            }
        }
    }
}

// ---------------------------------------------------------------------------
// Main kernel: 12 warps, token pair per warp — byte-identical to the
// verified 152 us kernel from R11/R12/R13.
// ---------------------------------------------------------------------------
#define NW 12
#define NTHREADS (NW * 32)

#define OFF_WA    0        // [32 i][9 b][32 lane]
#define OFF_WB    9216
#define OFF_WO    18432    // [32 c][9 b][32 o]
#define OFF_WM1   27648    // [32 c][32 o]
#define OFF_WM2   28672
#define OFF_STG   29696
// Per-warp staging: 32 rows x 32 floats (XOR-swizzled ulonglong2 slots),
// reused for pair-interleaved x THEN hidden.
#define STG_PER_WARP 1024
#define SMEM_FLOATS (OFF_STG + NW * STG_PER_WARP)
#define SMEM_BYTES  (SMEM_FLOATS * 4)      // 167,936 B

__global__ void __launch_bounds__(NTHREADS, 1)
gb_kernel(const float* __restrict__ mv,      // [ntok][32][16]
          const float* __restrict__ refmv,   // [ntok][16]
          const float* __restrict__ wLmv,
          const float* __restrict__ wRmv,
          const float* __restrict__ wJLmv,
          const float* __restrict__ wJRmv,
          const float* __restrict__ wOmv,    // [32 o][32 c][9 b]
          const float* __restrict__ wMvs2s,  // [64 o][32 c]
          float* __restrict__ out,           // [ntok][32][16]
          float* __restrict__ outS,          // [ntok][64]
          int ntok)
{
    extern __shared__ float sm[];
    float* WA  = sm + OFF_WA;
    float* WB  = sm + OFF_WB;
    float* WO  = sm + OFF_WO;
    float* WM1 = sm + OFF_WM1;
    float* WM2 = sm + OFF_WM2;

    const int tid  = threadIdx.x;
    const int lane = tid & 31;
    const int wid  = tid >> 5;

    // ---- stage mv weights (lane-permuted) ----
    // lane<16: A=left[lane], B=right[lane];  lane>=16: A=jl[l-16], B=jr[l-16]
    for (int idx = tid; idx < 9216; idx += NTHREADS) {
        const int l   = idx & 31;
        const int off = idx >> 5;               // i*9+b
        WA[idx] = (l < 16) ? wLmv[l * 288 + off] : wJLmv[(l - 16) * 288 + off];
        WB[idx] = (l < 16) ? wRmv[l * 288 + off] : wJRmv[(l - 16) * 288 + off];
        WO[idx] = wOmv[l * 288 + off];
    }
    for (int idx = tid; idx < 1024; idx += NTHREADS) {
        const int l = idx & 31;
        const int c = idx >> 5;
        WM1[idx] = wMvs2s[l * 32 + c];
        WM2[idx] = wMvs2s[(32 + l) * 32 + c];
    }
    __syncthreads();

    float* buf = sm + OFF_STG + wid * STG_PER_WARP; // 32 rows x 32 floats (swizzled)

    const int gw = blockIdx.x * NW + wid;
    const int nw = gridDim.x * NW;
    const int npair = ntok >> 1;

    for (int p = gw; p < npair; p += nw) {
        const int tA = 2 * p, tB = 2 * p + 1;

        // ---- stage token-pair inputs ----
        // Row i: logical ulonglong2 slot t holds blades (2t, 2t+1) pairs;
        // physical slot = t ^ (i & 7).
        const float4* gxA = reinterpret_cast<const float4*>(mv + (size_t)tA * 512);
        const float4* gxB = reinterpret_cast<const float4*>(mv + (size_t)tB * 512);
        #pragma unroll
        for (int it = 0; it < 4; ++it) {
            const int c = it * 32 + lane;        // chunk 0..127
            const int i = c >> 2, q = c & 3;     // channel, quarter (blades 4q..4q+3)
            const float4 a = gxA[c];
            const float4 b = gxB[c];
            const int m  = i & 7;
            const int p0 = (2 * q) ^ m;          // slot for blades 4q,4q+1
            const int p1 = p0 ^ 1;               // slot for blades 4q+2,4q+3
            float* base = buf + i * 32;
            *reinterpret_cast<float4*>(base + p0 * 4) = make_float4(a.x, b.x, a.y, b.y);
            *reinterpret_cast<float4*>(base + p1 * 4) = make_float4(a.z, b.z, a.w, b.w);
        }
        const ull refp = pack2(refmv[(size_t)tA * 16 + 15], refmv[(size_t)tB * 16 + 15]);
        const float* Pa = g_P + (size_t)tA * 160;
        const float* Pb = g_P + (size_t)tB * 160;
        __syncwarp();

        // ---- input equi-linears owned by this lane (packed pair) ----
        ull A[16], Bv[16];
        A[0]  = pack2(__ldg(Pa + lane),      __ldg(Pb + lane));
        Bv[0] = pack2(__ldg(Pa + 32 + lane), __ldg(Pb + 32 + lane));
        #pragma unroll
        for (int j = 1; j < 16; ++j) { A[j] = 0ULL; Bv[j] = 0ULL; }

        for (int i0 = 0; i0 < 32; i0 += 8) {
            #pragma unroll
            for (int k = 0; k < 8; ++k) {
                const int i = i0 + k;
                ull xr[16];
                const float* base = buf + i * 32;
                #pragma unroll
                for (int t = 0; t < 8; ++t) {    // broadcast reads, swizzled slots
                    const ulonglong2 v =
                        *reinterpret_cast<const ulonglong2*>(base + ((t ^ k) * 4));
                    xr[2*t] = v.x; xr[2*t+1] = v.y;
                }
                ull wa[9], wb[9];
                #pragma unroll
                for (int b = 0; b < 9; ++b) {
                    wa[b] = dup2(WA[(i * 9 + b) * 32 + lane]);
                    wb[b] = dup2(WB[(i * 9 + b) * 32 + lane]);
                }
                ga::linAcc2(A, wa, xr);
                ga::linAcc2(Bv, wb, xr);
            }
        }
        __syncwarp();   // all lanes done reading x staging

        // ---- bilinear: gp on lanes 0..15, join on lanes 16..31 ----
        ull h[16];
        #pragma unroll
        for (int j = 0; j < 16; ++j) h[j] = 0ULL;
        if (lane < 16) {
            ga::gpAll(A, Bv, h, typename ga::mkseq<16>::type{});
        } else {
            ga::jnAll(A, Bv, h, typename ga::mkseq<16>::type{});
            #pragma unroll
            for (int j = 0; j < 16; ++j) h[j] = mul2(h[j], refp);
        }
        // stage hidden (lane = channel) into the SAME buffer, swizzled
        {
            float* base = buf + lane * 32;
            const int m = lane & 7;
            #pragma unroll
            for (int t = 0; t < 8; ++t)
                *reinterpret_cast<ulonglong2*>(base + ((t ^ m) * 4)) =
                    make_ulonglong2(h[2*t], h[2*t+1]);
        }
        __syncwarp();

        // ---- output equi-linear + scalar heads: lane = output channel o ----
        ull O[16];
        O[0] = pack2(__ldg(Pa + 64 + lane), __ldg(Pb + 64 + lane));
        #pragma unroll
        for (int j = 1; j < 16; ++j) O[j] = 0ULL;
        ull os1 = pack2(__ldg(Pa + 96 + lane),  __ldg(Pb + 96 + lane));
        ull os2 = pack2(__ldg(Pa + 128 + lane), __ldg(Pb + 128 + lane));

        for (int c0 = 0; c0 < 32; c0 += 8) {
            #pragma unroll
            for (int k = 0; k < 8; ++k) {
                const int c = c0 + k;
                ull hr[16];
                const float* base = buf + c * 32;
                #pragma unroll
                for (int t = 0; t < 8; ++t) {    // broadcast reads, swizzled slots
                    const ulonglong2 v =
                        *reinterpret_cast<const ulonglong2*>(base + ((t ^ k) * 4));
                    hr[2*t] = v.x; hr[2*t+1] = v.y;
                }
                ull wo[9];
                #pragma unroll
                for (int b = 0; b < 9; ++b) wo[b] = dup2(WO[(c * 9 + b) * 32 + lane]);
                ga::linAcc2(O, wo, hr);

                os1 = fma2(dup2(WM1[c * 32 + lane]), hr[0], os1);
                os2 = fma2(dup2(WM2[c * 32 + lane]), hr[0], os2);
            }
        }

        // ---- write outputs ----
        {
            float Oa[16], Ob[16];
            #pragma unroll
            for (int j = 0; j < 16; ++j) unpack2(O[j], Oa[j], Ob[j]);
            float* omA = out + (size_t)tA * 512 + lane * 16;
            float* omB = out + (size_t)tB * 512 + lane * 16;
            #pragma unroll
            for (int m = 0; m < 4; ++m) {
                *reinterpret_cast<float4*>(omA + m * 4) =
                    make_float4(Oa[m*4+0], Oa[m*4+1], Oa[m*4+2], Oa[m*4+3]);
                *reinterpret_cast<float4*>(omB + m * 4) =
                    make_float4(Ob[m*4+0], Ob[m*4+1], Ob[m*4+2], Ob[m*4+3]);
            }
        }
        {
            float a1, b1, a2, b2;
            unpack2(os1, a1, b1);
            unpack2(os2, a2, b2);
            outS[(size_t)tA * 64 + lane]      = a1;
            outS[(size_t)tA * 64 + 32 + lane] = a2;
            outS[(size_t)tB * 64 + lane]      = b1;
            outS[(size_t)tB * 64 + 32 + lane] = b2;
        }
        __syncwarp();   // staging reused next iteration
    }
}

// ---------------------------------------------------------------------------
// Launch
// ---------------------------------------------------------------------------
extern "C" void kernel_launch(void* const* d_in, const int* in_sizes, int n_in,
                              void* d_out, int out_size) {
    const float* mv     = (const float*)d_in[0];
    const float* refmv  = (const float*)d_in[1];
    const float* scal   = (const float*)d_in[2];
    // d_in[3..5] = basis, gp, jn (structure hardcoded at compile time)
    const float* wLmv   = (const float*)d_in[6];
    const float* wLs    = (const float*)d_in[7];
    const float* wRmv   = (const float*)d_in[8];
    const float* wRs    = (const float*)d_in[9];
    const float* wJLmv  = (const float*)d_in[10];
    const float* wJLs   = (const float*)d_in[11];
    const float* wJRmv  = (const float*)d_in[12];
    const float* wJRs   = (const float*)d_in[13];
    const float* wOmv   = (const float*)d_in[14];
    const float* wS2mv  = (const float*)d_in[15];
    const float* wMvs2s = (const float*)d_in[16];
    const float* wS2s   = (const float*)d_in[17];

    const int ntok = in_sizes[0] / 512;          // 32768
    float* out  = (float*)d_out;                 // [ntok*512] out_mv
    float* outS = out + (size_t)ntok * 512;      // [ntok*64]  out_s

    int dev = 0;
    cudaGetDevice(&dev);
    int nsm = 148;
    cudaDeviceGetAttribute(&nsm, cudaDevAttrMultiProcessorCount, dev);

    // Stage 1: scalar-head matmul -> g_P (smem weights, conflict-free,
    // no artificial occupancy cap; 2 blocks/SM)
    scalar_head_kernel<<<2 * nsm, 256>>>(scal, wLs, wRs, wJLs, wJRs,
                                         wS2mv, wS2s, ntok);

    // Stage 2: main geometric-bilinear kernel (unchanged, verified 152 us)
    cudaFuncSetAttribute(gb_kernel, cudaFuncAttributeMaxDynamicSharedMemorySize, SMEM_BYTES);
    gb_kernel<<<nsm, NTHREADS, SMEM_BYTES>>>(
        mv, refmv,
        wLmv, wRmv, wJLmv, wJRmv, wOmv, wMvs2s,
        out, outS, ntok);
}

// round 15
// speedup vs baseline: 1.0542x; 1.0542x over previous
#include <cuda_runtime.h>
#include <cuda_fp16.h>
#include <cstdint>
#include <cstddef>

typedef unsigned long long ull;

// ---------------------------------------------------------------------------
// Packed f32x2 helpers (SASS FFMA2 path — only reachable via explicit PTX)
// ---------------------------------------------------------------------------
__device__ __forceinline__ ull fma2(ull a, ull b, ull c) {
    ull d; asm("fma.rn.f32x2 %0,%1,%2,%3;" : "=l"(d) : "l"(a), "l"(b), "l"(c)); return d;
}
__device__ __forceinline__ ull mul2(ull a, ull b) {
    ull d; asm("mul.rn.f32x2 %0,%1,%2;" : "=l"(d) : "l"(a), "l"(b)); return d;
}
__device__ __forceinline__ ull pack2(float lo, float hi) {
    ull d; asm("mov.b64 %0,{%1,%2};" : "=l"(d) : "f"(lo), "f"(hi)); return d;
}
__device__ __forceinline__ ull dup2(float x) {
    ull d; asm("mov.b64 %0,{%1,%1};" : "=l"(d) : "f"(x)); return d;
}
__device__ __forceinline__ void unpack2(ull a, float& lo, float& hi) {
    asm("mov.b64 {%0,%1},%2;" : "=f"(lo), "=f"(hi) : "l"(a));
}
__device__ __forceinline__ ull neg2(ull a) { return a ^ 0x8000000080000000ULL; }

// fp16x2 weight helpers: one LDS.32 carries TWO weights; convert to fp32 and
// duplicate into both f32x2 lanes.
__device__ __forceinline__ float h2lo(uint32_t u) {
    __half2 h = *reinterpret_cast<__half2*>(&u); return __low2float(h);
}
__device__ __forceinline__ float h2hi(uint32_t u) {
    __half2 h = *reinterpret_cast<__half2*>(&u); return __high2float(h);
}
__device__ __forceinline__ void h2d(uint32_t u, ull& a, ull& b) {
    a = dup2(h2lo(u)); b = dup2(h2hi(u));
}
__device__ __forceinline__ uint32_t packh2(float x, float y) {
    __half2 h = __floats2half2_rn(x, y);
    return *reinterpret_cast<uint32_t*>(&h);
}

// ---------------------------------------------------------------------------
// Compile-time PGA(3,0,1) tables. Blade order matches the reference:
// idx : (), e0,e1,e2,e3, e01,e02,e03,e12,e13,e23, e012,e013,e023,e123, e0123
// ---------------------------------------------------------------------------
namespace ga {

__host__ __device__ constexpr unsigned bladeMask(int i) {
    constexpr unsigned m[16] = {0u,1u,2u,4u,8u, 3u,5u,9u,6u,10u,12u, 7u,11u,13u,14u, 15u};
    return m[i];
}
__host__ __device__ constexpr int idxOfMask(unsigned m) {
    constexpr int t[16] = {0,1,2,5,3,6,8,11,4,7,9,12,10,13,14,15};
    return t[m];
}
__host__ __device__ constexpr int invCnt(unsigned a, unsigned b) {
    int s = 0;
    for (int i = 0; i < 4; ++i)
        if ((b >> i) & 1u)
            for (int j = i + 1; j < 4; ++j)
                if ((a >> j) & 1u) ++s;
    return s;
}
__host__ __device__ constexpr float gpSign(int j, int k) {
    unsigned a = bladeMask(j), b = bladeMask(k);
    if (a & b & 1u) return 0.0f;                   // e0*e0 = 0
    return (invCnt(a, b) & 1) ? -1.0f : 1.0f;
}
__host__ __device__ constexpr int gpTgt(int j, int k) {
    return idxOfMask(bladeMask(j) ^ bladeMask(k));
}
__host__ __device__ constexpr float dSign(int t) {
    unsigned m = bladeMask(t);
    return (invCnt(m, 15u ^ m) & 1) ? -1.0f : 1.0f;
}
__host__ __device__ constexpr float jnCoef(int b, int c) {
    unsigned mb = bladeMask(b), mc = bladeMask(c);
    if ((mb | mc) != 15u) return 0.0f;
    unsigned ma = mb & mc;
    int ia = idxOfMask(15u ^ ma);
    unsigned cb = 15u ^ mb, cc = 15u ^ mc;
    float so = (invCnt(cb, cc) & 1) ? -1.0f : 1.0f;
    return dSign(ia) * so * dSign(b) * dSign(c);
}
__host__ __device__ constexpr int jnTgt(int b, int c) {
    return idxOfMask(bladeMask(b) & bladeMask(c));
}

template<int...> struct iseq {};
template<int N, int... S> struct mkseq : mkseq<N-1, N-1, S...> {};
template<int... S> struct mkseq<0, S...> { using type = iseq<S...>; };

// Row-local negation: only neg2(L[J]) for the CURRENT row is live.
template<int J, int K>
__device__ __forceinline__ void gpTerm(ull aj, ull naj, const ull (&R)[16], ull (&h)[16]) {
    constexpr float s = gpSign(J, K);
    if constexpr (s > 0.5f) {
        constexpr int t = gpTgt(J, K);
        h[t] = fma2(aj, R[K], h[t]);
    } else if constexpr (s < -0.5f) {
        constexpr int t = gpTgt(J, K);
        h[t] = fma2(naj, R[K], h[t]);
    }
}
template<int J, int... Ks>
__device__ __forceinline__ void gpRow(const ull (&L)[16], const ull (&R)[16],
                                      ull (&h)[16], iseq<Ks...>) {
    const ull aj  = L[J];
    const ull naj = neg2(aj);
    (gpTerm<J, Ks>(aj, naj, R, h), ...);
}
template<int... Js>
__device__ __forceinline__ void gpAll(const ull (&L)[16], const ull (&R)[16],
                                      ull (&h)[16], iseq<Js...>) {
    (gpRow<Js>(L, R, h, typename mkseq<16>::type{}), ...);
}

template<int J, int K>
__device__ __forceinline__ void jnTerm(ull aj, ull naj, const ull (&R)[16], ull (&h)[16]) {
    constexpr float s = jnCoef(J, K);
    if constexpr (s > 0.5f) {
        constexpr int t = jnTgt(J, K);
        h[t] = fma2(aj, R[K], h[t]);
    } else if constexpr (s < -0.5f) {
        constexpr int t = jnTgt(J, K);
        h[t] = fma2(naj, R[K], h[t]);
    }
}
template<int J, int... Ks>
__device__ __forceinline__ void jnRow(const ull (&L)[16], const ull (&R)[16],
                                      ull (&h)[16], iseq<Ks...>) {
    const ull aj  = L[J];
    const ull naj = neg2(aj);
    (jnTerm<J, Ks>(aj, naj, R, h), ...);
}
template<int... Js>
__device__ __forceinline__ void jnAll(const ull (&L)[16], const ull (&R)[16],
                                      ull (&h)[16], iseq<Js...>) {
    (jnRow<Js>(L, R, h, typename mkseq<16>::type{}), ...);
}

// Equivariant-linear accumulation (packed pair), one input channel.
// grades = [0,1,1,1,1, 2,2,2,2,2,2, 3,3,3,3, 4]
// e0 wedge (+1): 1<-0 (w5); 5,6,7<-2,3,4 (w6); 11,12,13<-8,9,10 (w7); 15<-14 (w8)
__device__ __forceinline__ void linAcc2(ull (&o)[16], const ull (&w)[9], const ull (&x)[16]) {
    o[0]  = fma2(w[0], x[0],  o[0]);
    o[1]  = fma2(w[1], x[1],  o[1]);  o[1]  = fma2(w[5], x[0],  o[1]);
    o[2]  = fma2(w[1], x[2],  o[2]);
    o[3]  = fma2(w[1], x[3],  o[3]);
    o[4]  = fma2(w[1], x[4],  o[4]);
    o[5]  = fma2(w[2], x[5],  o[5]);  o[5]  = fma2(w[6], x[2],  o[5]);
    o[6]  = fma2(w[2], x[6],  o[6]);  o[6]  = fma2(w[6], x[3],  o[6]);
    o[7]  = fma2(w[2], x[7],  o[7]);  o[7]  = fma2(w[6], x[4],  o[7]);
    o[8]  = fma2(w[2], x[8],  o[8]);
    o[9]  = fma2(w[2], x[9],  o[9]);
    o[10] = fma2(w[2], x[10], o[10]);
    o[11] = fma2(w[3], x[11], o[11]); o[11] = fma2(w[7], x[8],  o[11]);
    o[12] = fma2(w[3], x[12], o[12]); o[12] = fma2(w[7], x[9],  o[12]);
    o[13] = fma2(w[3], x[13], o[13]); o[13] = fma2(w[7], x[10], o[13]);
    o[14] = fma2(w[3], x[14], o[14]);
    o[15] = fma2(w[4], x[15], o[15]); o[15] = fma2(w[8], x[14], o[15]);
}

} // namespace ga

// ---------------------------------------------------------------------------
// Stage-0/1 (VERBATIM from R12, the measured-best arrangement).
// g_T[64 s][160 c]: pre-transposed scalar-head weights (fp32)
// g_P[tok][160]: per-token scalar-head results
//   [0:32)=A0, [32:64)=B0, [64:96)=O0, [96:128)=s1, [128:160)=s2
// ---------------------------------------------------------------------------
#define MAX_TOK 32768
__device__ float g_T[64 * 160];
__device__ float g_P[MAX_TOK * 160];

__global__ void init_transpose(const float* __restrict__ wLs, const float* __restrict__ wRs,
                               const float* __restrict__ wJLs, const float* __restrict__ wJRs,
                               const float* __restrict__ wS2mv, const float* __restrict__ wS2s)
{
    const int idx = blockIdx.x * blockDim.x + threadIdx.x;
    if (idx >= 64 * 160) return;
    const int s = idx / 160;
    const int c = idx - s * 160;
    const int g = c >> 5;
    const int k = c & 31;
    float v;
    if (g == 0)      v = (k < 16) ? wLs[k * 64 + s] : wJLs[(k - 16) * 64 + s];
    else if (g == 1) v = (k < 16) ? wRs[k * 64 + s] : wJRs[(k - 16) * 64 + s];
    else if (g == 2) v = wS2mv[k * 64 + s];
    else if (g == 3) v = wS2s[k * 64 + s];
    else             v = wS2s[(32 + k) * 64 + s];
    g_T[idx] = v;
}

__global__ void __launch_bounds__(256, 1)
scalar_head_kernel(const float* __restrict__ scal, int ntok)
{
    const int lane = threadIdx.x & 31;
    const int wid  = threadIdx.x >> 5;
    const int gw   = blockIdx.x * 8 + wid;
    const int nw   = gridDim.x * 8;
    const int noct = ntok >> 3;

    for (int o = gw; o < noct; o += nw) {
        const int t0 = o * 8;
        ull acc[5][4];
        #pragma unroll
        for (int g = 0; g < 5; ++g)
            #pragma unroll
            for (int u = 0; u < 4; ++u) acc[g][u] = 0ULL;

        for (int s4 = 0; s4 < 16; ++s4) {
            float4 sv[8];
            #pragma unroll
            for (int t = 0; t < 8; ++t)
                sv[t] = __ldg(reinterpret_cast<const float4*>(scal + (size_t)(t0 + t) * 64) + s4);
            #pragma unroll
            for (int k = 0; k < 4; ++k) {
                const int s = s4 * 4 + k;
                const float* ts = g_T + s * 160 + lane;
                const ull w0 = dup2(__ldg(ts));
                const ull w1 = dup2(__ldg(ts + 32));
                const ull w2 = dup2(__ldg(ts + 64));
                const ull w3 = dup2(__ldg(ts + 96));
                const ull w4 = dup2(__ldg(ts + 128));
                #pragma unroll
                for (int u = 0; u < 4; ++u) {
                    const float xa = (k == 0) ? sv[2*u].x : (k == 1) ? sv[2*u].y
                                   : (k == 2) ? sv[2*u].z : sv[2*u].w;
                    const float xb = (k == 0) ? sv[2*u+1].x : (k == 1) ? sv[2*u+1].y
                                   : (k == 2) ? sv[2*u+1].z : sv[2*u+1].w;
                    const ull x = pack2(xa, xb);
                    acc[0][u] = fma2(w0, x, acc[0][u]);
                    acc[1][u] = fma2(w1, x, acc[1][u]);
                    acc[2][u] = fma2(w2, x, acc[2][u]);
                    acc[3][u] = fma2(w3, x, acc[3][u]);
                    acc[4][u] = fma2(w4, x, acc[4][u]);
                }
            }
        }
        #pragma unroll
        for (int u = 0; u < 4; ++u) {
            float* pa = g_P + (size_t)(t0 + 2*u)     * 160 + lane;
            float* pb = g_P + (size_t)(t0 + 2*u + 1) * 160 + lane;
            #pragma unroll
            for (int g = 0; g < 5; ++g) {
                float a, b;
                unpack2(acc[g][u], a, b);
                pa[g * 32] = a;
                pb[g * 32] = b;
            }
        }
    }
}

// ---------------------------------------------------------------------------
// Main kernel: 12 warps, token pair per warp. Same structure as the verified
// 152 us kernel, but mv weights stored in smem as fp16x2 PAIRS:
//   WAH/WBH/WOH: [i(32)][p(5)][lane(32)] u32; u32 p holds weights (2p, 2p+1),
//   p=4 holds (w8, 0). WMH: [c][lane] u32 = (wm1, wm2).
// Weight LDS wavefronts per pair: 928 -> 512.
// ---------------------------------------------------------------------------
#define NW 12
#define NTHREADS (NW * 32)

#define OFF_WAH   0        // 5120 u32
#define OFF_WBH   5120
#define OFF_WOH   10240
#define OFF_WMH   15360    // 1024 u32
#define OFF_STG   16384
#define STG_PER_WARP 1024
#define SMEM_FLOATS (OFF_STG + NW * STG_PER_WARP)
#define SMEM_BYTES  (SMEM_FLOATS * 4)      // 114,688 B

__global__ void __launch_bounds__(NTHREADS, 1)
gb_kernel(const float* __restrict__ mv,      // [ntok][32][16]
          const float* __restrict__ refmv,   // [ntok][16]
          const float* __restrict__ wLmv,
          const float* __restrict__ wRmv,
          const float* __restrict__ wJLmv,
          const float* __restrict__ wJRmv,
          const float* __restrict__ wOmv,    // [32 o][32 c][9 b]
          const float* __restrict__ wMvs2s,  // [64 o][32 c]
          float* __restrict__ out,           // [ntok][32][16]
          float* __restrict__ outS,          // [ntok][64]
          int ntok)
{
    extern __shared__ float sm[];
    uint32_t* WAH = reinterpret_cast<uint32_t*>(sm + OFF_WAH);
    uint32_t* WBH = reinterpret_cast<uint32_t*>(sm + OFF_WBH);
    uint32_t* WOH = reinterpret_cast<uint32_t*>(sm + OFF_WOH);
    uint32_t* WMH = reinterpret_cast<uint32_t*>(sm + OFF_WMH);

    const int tid  = threadIdx.x;
    const int lane = tid & 31;
    const int wid  = tid >> 5;

    // ---- stage mv weights (lane-permuted, fp32 -> fp16x2 pairs) ----
    // lane<16: A=left[lane], B=right[lane];  lane>=16: A=jl[l-16], B=jr[l-16]
    for (int idx = tid; idx < 5120; idx += NTHREADS) {
        const int l = idx & 31;
        const int r = idx >> 5;                 // i*5 + p
        const int i = r / 5, p = r - 5 * i;
        const int b0 = 2 * p;
        const float* srcA = (l < 16) ? (wLmv + l * 288) : (wJLmv + (l - 16) * 288);
        const float* srcB = (l < 16) ? (wRmv + l * 288) : (wJRmv + (l - 16) * 288);
        const float a0 = srcA[i * 9 + b0];
        const float a1 = (p < 4) ? srcA[i * 9 + b0 + 1] : 0.0f;
        const float c0 = srcB[i * 9 + b0];
        const float c1 = (p < 4) ? srcB[i * 9 + b0 + 1] : 0.0f;
        WAH[idx] = packh2(a0, a1);
        WBH[idx] = packh2(c0, c1);
        const float o0 = wOmv[l * 288 + i * 9 + b0];
        const float o1 = (p < 4) ? wOmv[l * 288 + i * 9 + b0 + 1] : 0.0f;
        WOH[idx] = packh2(o0, o1);
    }
    for (int idx = tid; idx < 1024; idx += NTHREADS) {
        const int l = idx & 31;
        const int c = idx >> 5;
        WMH[idx] = packh2(wMvs2s[l * 32 + c], wMvs2s[(32 + l) * 32 + c]);
    }
    __syncthreads();

    float* buf = sm + OFF_STG + wid * STG_PER_WARP; // 32 rows x 32 floats (swizzled)

    const int gw = blockIdx.x * NW + wid;
    const int nw = gridDim.x * NW;
    const int npair = ntok >> 1;

    for (int p = gw; p < npair; p += nw) {
        const int tA = 2 * p, tB = 2 * p + 1;

        // ---- stage token-pair inputs ----
        // Row i: logical ulonglong2 slot t holds blades (2t, 2t+1) pairs;
        // physical slot = t ^ (i & 7).
        const float4* gxA = reinterpret_cast<const float4*>(mv + (size_t)tA * 512);
        const float4* gxB = reinterpret_cast<const float4*>(mv + (size_t)tB * 512);
        #pragma unroll
        for (int it = 0; it < 4; ++it) {
            const int c = it * 32 + lane;        // chunk 0..127
            const int i = c >> 2, q = c & 3;     // channel, quarter (blades 4q..4q+3)
            const float4 a = gxA[c];
            const float4 b = gxB[c];
            const int m  = i & 7;
            const int p0 = (2 * q) ^ m;          // slot for blades 4q,4q+1
            const int p1 = p0 ^ 1;               // slot for blades 4q+2,4q+3
            float* base = buf + i * 32;
            *reinterpret_cast<float4*>(base + p0 * 4) = make_float4(a.x, b.x, a.y, b.y);
            *reinterpret_cast<float4*>(base + p1 * 4) = make_float4(a.z, b.z, a.w, b.w);
        }
        const ull refp = pack2(refmv[(size_t)tA * 16 + 15], refmv[(size_t)tB * 16 + 15]);
        const float* Pa = g_P + (size_t)tA * 160;
        const float* Pb = g_P + (size_t)tB * 160;
        __syncwarp();

        // ---- input equi-linears owned by this lane (packed pair) ----
        ull A[16], Bv[16];
        A[0]  = pack2(__ldg(Pa + lane),      __ldg(Pb + lane));
        Bv[0] = pack2(__ldg(Pa + 32 + lane), __ldg(Pb + 32 + lane));
        #pragma unroll
        for (int j = 1; j < 16; ++j) { A[j] = 0ULL; Bv[j] = 0ULL; }

        for (int i0 = 0; i0 < 32; i0 += 8) {
            #pragma unroll
            for (int k = 0; k < 8; ++k) {
                const int i = i0 + k;
                ull xr[16];
                const float* base = buf + i * 32;
                #pragma unroll
                for (int t = 0; t < 8; ++t) {    // broadcast reads, swizzled slots
                    const ulonglong2 v =
                        *reinterpret_cast<const ulonglong2*>(base + ((t ^ k) * 4));
                    xr[2*t] = v.x; xr[2*t+1] = v.y;
                }
                ull wa[9], wb[9];
                {
                    const uint32_t* ba = WAH + (i * 5) * 32 + lane;
                    const uint32_t* bb = WBH + (i * 5) * 32 + lane;
                    h2d(ba[0],   wa[0], wa[1]);
                    h2d(ba[32],  wa[2], wa[3]);
                    h2d(ba[64],  wa[4], wa[5]);
                    h2d(ba[96],  wa[6], wa[7]);
                    wa[8] = dup2(h2lo(ba[128]));
                    h2d(bb[0],   wb[0], wb[1]);
                    h2d(bb[32],  wb[2], wb[3]);
                    h2d(bb[64],  wb[4], wb[5]);
                    h2d(bb[96],  wb[6], wb[7]);
                    wb[8] = dup2(h2lo(bb[128]));
                }
                ga::linAcc2(A, wa, xr);
                ga::linAcc2(Bv, wb, xr);
            }
        }
        __syncwarp();   // all lanes done reading x staging

        // ---- bilinear: gp on lanes 0..15, join on lanes 16..31 ----
        ull h[16];
        #pragma unroll
        for (int j = 0; j < 16; ++j) h[j] = 0ULL;
        if (lane < 16) {
            ga::gpAll(A, Bv, h, typename ga::mkseq<16>::type{});
        } else {
            ga::jnAll(A, Bv, h, typename ga::mkseq<16>::type{});
            #pragma unroll
            for (int j = 0; j < 16; ++j) h[j] = mul2(h[j], refp);
        }
        // stage hidden (lane = channel) into the SAME buffer, swizzled
        {
            float* base = buf + lane * 32;
            const int m = lane & 7;
            #pragma unroll
            for (int t = 0; t < 8; ++t)
                *reinterpret_cast<ulonglong2*>(base + ((t ^ m) * 4)) =
                    make_ulonglong2(h[2*t], h[2*t+1]);
        }
        __syncwarp();

        // ---- output equi-linear + scalar heads: lane = output channel o ----
        ull O[16];
        O[0] = pack2(__ldg(Pa + 64 + lane), __ldg(Pb + 64 + lane));
        #pragma unroll
        for (int j = 1; j < 16; ++j) O[j] = 0ULL;
        ull os1 = pack2(__ldg(Pa + 96 + lane),  __ldg(Pb + 96 + lane));
        ull os2 = pack2(__ldg(Pa + 128 + lane), __ldg(Pb + 128 + lane));

        for (int c0 = 0; c0 < 32; c0 += 8) {
            #pragma unroll
            for (int k = 0; k < 8; ++k) {
                const int c = c0 + k;
                ull hr[16];
                const float* base = buf + c * 32;
                #pragma unroll
                for (int t = 0; t < 8; ++t) {    // broadcast reads, swizzled slots
                    const ulonglong2 v =
                        *reinterpret_cast<const ulonglong2*>(base + ((t ^ k) * 4));
                    hr[2*t] = v.x; hr[2*t+1] = v.y;
                }
                ull wo[9];
                {
                    const uint32_t* bo = WOH + (c * 5) * 32 + lane;
                    h2d(bo[0],   wo[0], wo[1]);
                    h2d(bo[32],  wo[2], wo[3]);
                    h2d(bo[64],  wo[4], wo[5]);
                    h2d(bo[96],  wo[6], wo[7]);
                    wo[8] = dup2(h2lo(bo[128]));
                }
                ga::linAcc2(O, wo, hr);

                const uint32_t um = WMH[c * 32 + lane];
                os1 = fma2(dup2(h2lo(um)), hr[0], os1);
                os2 = fma2(dup2(h2hi(um)), hr[0], os2);
            }
        }

        // ---- write outputs ----
        {
            float Oa[16], Ob[16];
            #pragma unroll
            for (int j = 0; j < 16; ++j) unpack2(O[j], Oa[j], Ob[j]);
            float* omA = out + (size_t)tA * 512 + lane * 16;
            float* omB = out + (size_t)tB * 512 + lane * 16;
            #pragma unroll
            for (int m = 0; m < 4; ++m) {
                *reinterpret_cast<float4*>(omA + m * 4) =
                    make_float4(Oa[m*4+0], Oa[m*4+1], Oa[m*4+2], Oa[m*4+3]);
                *reinterpret_cast<float4*>(omB + m * 4) =
                    make_float4(Ob[m*4+0], Ob[m*4+1], Ob[m*4+2], Ob[m*4+3]);
            }
        }
        {
            float a1, b1, a2, b2;
            unpack2(os1, a1, b1);
            unpack2(os2, a2, b2);
            outS[(size_t)tA * 64 + lane]      = a1;
            outS[(size_t)tA * 64 + 32 + lane] = a2;
            outS[(size_t)tB * 64 + lane]      = b1;
            outS[(size_t)tB * 64 + 32 + lane] = b2;
        }
        __syncwarp();   // staging reused next iteration
    }
}

// ---------------------------------------------------------------------------
// Launch
// ---------------------------------------------------------------------------
extern "C" void kernel_launch(void* const* d_in, const int* in_sizes, int n_in,
                              void* d_out, int out_size) {
    const float* mv     = (const float*)d_in[0];
    const float* refmv  = (const float*)d_in[1];
    const float* scal   = (const float*)d_in[2];
    // d_in[3..5] = basis, gp, jn (structure hardcoded at compile time)
    const float* wLmv   = (const float*)d_in[6];
    const float* wLs    = (const float*)d_in[7];
    const float* wRmv   = (const float*)d_in[8];
    const float* wRs    = (const float*)d_in[9];
    const float* wJLmv  = (const float*)d_in[10];
    const float* wJLs   = (const float*)d_in[11];
    const float* wJRmv  = (const float*)d_in[12];
    const float* wJRs   = (const float*)d_in[13];
    const float* wOmv   = (const float*)d_in[14];
    const float* wS2mv  = (const float*)d_in[15];
    const float* wMvs2s = (const float*)d_in[16];
    const float* wS2s   = (const float*)d_in[17];

    const int ntok = in_sizes[0] / 512;          // 32768
    float* out  = (float*)d_out;                 // [ntok*512] out_mv
    float* outS = out + (size_t)ntok * 512;      // [ntok*64]  out_s

    int dev = 0;
    cudaGetDevice(&dev);
    int nsm = 148;
    cudaDeviceGetAttribute(&nsm, cudaDevAttrMultiProcessorCount, dev);

    // Stage 0+1: verbatim R12 (measured-best): one-shot transpose, then
    // scalar-head matmul -> g_P.
    init_transpose<<<40, 256>>>(wLs, wRs, wJLs, wJRs, wS2mv, wS2s);
    scalar_head_kernel<<<2 * nsm, 256>>>(scal, ntok);

    // Stage 2: main geometric-bilinear kernel (fp16x2-packed weights)
    cudaFuncSetAttribute(gb_kernel, cudaFuncAttributeMaxDynamicSharedMemorySize, SMEM_BYTES);
    gb_kernel<<<nsm, NTHREADS, SMEM_BYTES>>>(
        mv, refmv,
        wLmv, wRmv, wJLmv, wJRmv, wOmv, wMvs2s,
        out, outS, ntok);
}